// round 5
// baseline (speedup 1.0000x reference)
#include <cuda_runtime.h>
#include <cuda_bf16.h>
#include <stdint.h>

#define NTOK 2048
#define HDIM 1024
#define IDIM 2048
#define NEXP 8
#define TOPK 2
#define NK (NTOK*TOPK)
#define WELEM (NEXP*IDIM*HDIM)

// ---------------- scratch (device globals) ----------------
__device__ int   g_ctr[2*NEXP];
__device__ int   g_offsets[NEXP+1];
__device__ int   g_topk_idx[NK];
__device__ float g_topk_w[NK];
__device__ int   g_perm_tok[NK];
__device__ int   g_slot_of[NK];
__device__ __nv_bfloat16 g_mid_hi[(size_t)(NK+128)*IDIM];
__device__ __nv_bfloat16 g_mid_lo[(size_t)(NK+128)*IDIM];
__device__ float g_down[(size_t)(NK+128)*HDIM];
// pre-split bf16 operands
__device__ __nv_bfloat16 g_x_hi[(size_t)NTOK*HDIM], g_x_lo[(size_t)NTOK*HDIM];
__device__ __nv_bfloat16 g_wg_hi[(size_t)WELEM], g_wg_lo[(size_t)WELEM];
__device__ __nv_bfloat16 g_wu_hi[(size_t)WELEM], g_wu_lo[(size_t)WELEM];
__device__ __nv_bfloat16 g_wd_hi[(size_t)WELEM], g_wd_lo[(size_t)WELEM];

// ---------------- helpers ----------------
__device__ __forceinline__ uint32_t smem_u32(const void* p){
    uint32_t a;
    asm("{ .reg .u64 t; cvta.to.shared.u64 t, %1; cvt.u32.u64 %0, t; }" : "=r"(a) : "l"(p));
    return a;
}
// swizzled 16B-chunk offset within a 128-row x 32-col bf16 tile (64B rows)
#define SWZ(row, c) ((uint32_t)(row)*64u + ((((uint32_t)(c)) ^ ((((uint32_t)(row))>>1)&3u))<<4))

#define CPA16(dst, src, sz) \
    asm volatile("cp.async.cg.shared.global [%0], [%1], 16, %2;" \
                 :: "r"(dst), "l"(src), "r"(sz))
#define CPA_COMMIT() asm volatile("cp.async.commit_group;")
#define CPA_WAIT(n)  asm volatile("cp.async.wait_group %0;" :: "n"(n))

#define LDSM4(r0,r1,r2,r3,addr) \
    asm volatile("ldmatrix.sync.aligned.m8n8.x4.shared.b16 {%0,%1,%2,%3}, [%4];" \
                 : "=r"(r0),"=r"(r1),"=r"(r2),"=r"(r3) : "r"(addr))

#define MMA_BF16(d, a, b0, b1) \
    asm volatile("mma.sync.aligned.m16n8k16.row.col.f32.bf16.bf16.f32 " \
        "{%0,%1,%2,%3}, {%4,%5,%6,%7}, {%8,%9}, {%0,%1,%2,%3};" \
        : "+f"((d)[0]), "+f"((d)[1]), "+f"((d)[2]), "+f"((d)[3]) \
        : "r"((a)[0]), "r"((a)[1]), "r"((a)[2]), "r"((a)[3]), "r"(b0), "r"(b1))

__device__ __forceinline__ void splitf4(float4 v, uint2& hi, uint2& lo){
    __nv_bfloat162 h01 = __float22bfloat162_rn(make_float2(v.x, v.y));
    __nv_bfloat162 h23 = __float22bfloat162_rn(make_float2(v.z, v.w));
    float2 f01 = __bfloat1622float2(h01), f23 = __bfloat1622float2(h23);
    __nv_bfloat162 l01 = __float22bfloat162_rn(make_float2(v.x - f01.x, v.y - f01.y));
    __nv_bfloat162 l23 = __float22bfloat162_rn(make_float2(v.z - f23.x, v.w - f23.y));
    hi = make_uint2(*reinterpret_cast<uint32_t*>(&h01), *reinterpret_cast<uint32_t*>(&h23));
    lo = make_uint2(*reinterpret_cast<uint32_t*>(&l01), *reinterpret_cast<uint32_t*>(&l23));
}

// ---------------- fp32 -> bf16 hi/lo split (grid-stride) ----------------
__global__ void cvt_kernel(const float4* __restrict__ src,
                           uint2* __restrict__ hi, uint2* __restrict__ lo, int n4) {
    for (int i = blockIdx.x * blockDim.x + threadIdx.x; i < n4;
         i += gridDim.x * blockDim.x) {
        uint2 h, l;
        splitf4(src[i], h, l);
        hi[i] = h; lo[i] = l;
    }
}

// ---------------- router ----------------
__global__ void router_kernel(const float* __restrict__ x, const float* __restrict__ Wr) {
    int warp = (blockIdx.x * blockDim.x + threadIdx.x) >> 5;
    int lane = threadIdx.x & 31;
    if (warp >= NTOK) return;
    const float* xr = x + (size_t)warp * HDIM;
    float acc[NEXP];
#pragma unroll
    for (int e = 0; e < NEXP; e++) acc[e] = 0.f;
    for (int h = lane; h < HDIM; h += 32) {
        float xv = xr[h];
#pragma unroll
        for (int e = 0; e < NEXP; e++) acc[e] += xv * Wr[e*HDIM + h];
    }
#pragma unroll
    for (int e = 0; e < NEXP; e++) {
#pragma unroll
        for (int off = 16; off > 0; off >>= 1)
            acc[e] += __shfl_xor_sync(0xFFFFFFFFu, acc[e], off);
    }
    if (lane == 0) {
        int i0 = 0; float v0 = acc[0];
#pragma unroll
        for (int e = 1; e < NEXP; e++) if (acc[e] > v0) { v0 = acc[e]; i0 = e; }
        int i1 = -1; float v1 = -1e30f;
#pragma unroll
        for (int e = 0; e < NEXP; e++) if (e != i0 && acc[e] > v1) { v1 = acc[e]; i1 = e; }
        float r = __expf(v1 - v0);
        float inv = 1.f / (1.f + r);
        g_topk_idx[2*warp]   = i0;  g_topk_w[2*warp]   = inv;
        g_topk_idx[2*warp+1] = i1;  g_topk_w[2*warp+1] = r * inv;
        atomicAdd(&g_ctr[i0], 1);
        atomicAdd(&g_ctr[i1], 1);
    }
}

// ---------------- scan + aux ----------------
__global__ void scan_kernel(float* __restrict__ aux_out) {
    if (threadIdx.x != 0) return;
    int off = 0;
#pragma unroll
    for (int e = 0; e < NEXP; e++) { g_offsets[e] = off; off += g_ctr[e]; }
    g_offsets[NEXP] = off;
    if (aux_out) {
        float mean = (float)TOPK / (float)NEXP;
        float var = 0.f;
#pragma unroll
        for (int e = 0; e < NEXP; e++) {
            float v = (float)g_ctr[e] / (float)NTOK - mean;
            var += v * v;
        }
        *aux_out = var / (float)(NEXP - 1) * (float)NEXP;
    }
}

// ---------------- slot assignment ----------------
__global__ void assign_kernel() {
    int tk = blockIdx.x * blockDim.x + threadIdx.x;
    if (tk >= NK) return;
    int e = g_topk_idx[tk];
    int pos = g_offsets[e] + atomicAdd(&g_ctr[NEXP + e], 1);
    g_perm_tok[pos] = tk >> 1;
    g_slot_of[tk] = pos;
}

// ---------------- gate+up bf16x3 mma GEMM (pre-split operands) ----------------
// stage: AH 0, AL 8192, GH 16384, GL 24576, UH 32768, UL 40960 ; stride 49152 ; 3 stages
#define GU_STG 49152
#define GU_NSTG 3
#define GU_SMEM (GU_NSTG*GU_STG)

__global__ __launch_bounds__(256,1) void gateup_mma() {
    const int e = blockIdx.z;
    const int seg0 = g_offsets[e];
    const int segLen = g_offsets[e+1] - seg0;
    const int m0 = blockIdx.y * 128;
    if (m0 >= segLen) return;
    const int n0 = blockIdx.x * 128;

    extern __shared__ char smc[];
    const uint32_t sb = smem_u32(smc);
    const int t = threadIdx.x, lane = t & 31, wid = t >> 5;
    const int wm = wid >> 2, wn = wid & 3;
    const int r = t & 127, half = t >> 7;

    int rowtok = (m0 + r < segLen) ? g_perm_tok[seg0 + m0 + r] : -1;
    const __nv_bfloat16* sAH = g_x_hi + (size_t)(rowtok >= 0 ? rowtok : 0)*HDIM;
    const __nv_bfloat16* sAL = g_x_lo + (size_t)(rowtok >= 0 ? rowtok : 0)*HDIM;
    const int szA = (rowtok >= 0) ? 16 : 0;
    const size_t wrow = ((size_t)e*IDIM + n0 + r)*HDIM;
    const __nv_bfloat16* sGH = g_wg_hi + wrow; const __nv_bfloat16* sGL = g_wg_lo + wrow;
    const __nv_bfloat16* sUH = g_wu_hi + wrow; const __nv_bfloat16* sUL = g_wu_lo + wrow;

    float cg[4][4][4] = {}, cu[4][4][4] = {};

    auto load_stage = [&](int ss){
        const uint32_t base = sb + (ss % GU_NSTG)*GU_STG;
        const int k0 = ss*32;
#pragma unroll
        for (int qq = 0; qq < 2; qq++) {
            const int c = 2*half + qq;
            const uint32_t dsw = SWZ(r, c);
            const int ko = k0 + c*8;
            CPA16(base +     0 + dsw, sAH + ko, szA);
            CPA16(base +  8192 + dsw, sAL + ko, szA);
            CPA16(base + 16384 + dsw, sGH + ko, 16);
            CPA16(base + 24576 + dsw, sGL + ko, 16);
            CPA16(base + 32768 + dsw, sUH + ko, 16);
            CPA16(base + 40960 + dsw, sUL + ko, 16);
        }
        CPA_COMMIT();
    };

    load_stage(0);
    load_stage(1);

#pragma unroll 1
    for (int s = 0; s < 32; ++s) {
        CPA_WAIT(1);
        __syncthreads();
        if (s + 2 < 32) load_stage(s + 2);
        const uint32_t base = sb + (s % GU_NSTG)*GU_STG;
#pragma unroll
        for (int k16 = 0; k16 < 2; k16++) {
            const int hc = lane >> 4, br = lane & 15;
            const int cc = k16*2 + hc;
            uint32_t ah[4][4], al[4][4];
#pragma unroll
            for (int i = 0; i < 4; i++) {
                int row = wm*64 + i*16 + br;
                uint32_t off = SWZ(row, cc);
                LDSM4(ah[i][0],ah[i][1],ah[i][2],ah[i][3], base +    0 + off);
                LDSM4(al[i][0],al[i][1],al[i][2],al[i][3], base + 8192 + off);
            }
#pragma unroll
            for (int p = 0; p < 2; p++) {
                int row = wn*32 + p*16 + br;
                uint32_t off = SWZ(row, cc);
                uint32_t g0,g1,g2,g3, h0,h1,h2,h3, u0,u1,u2,u3, w0,w1,w2,w3;
                LDSM4(g0,g1,g2,g3, base + 16384 + off);
                LDSM4(h0,h1,h2,h3, base + 24576 + off);
                LDSM4(u0,u1,u2,u3, base + 32768 + off);
                LDSM4(w0,w1,w2,w3, base + 40960 + off);
#pragma unroll
                for (int i = 0; i < 4; i++) {
                    MMA_BF16(cg[i][p*2],   ah[i], g0, g2);
                    MMA_BF16(cg[i][p*2],   ah[i], h0, h2);
                    MMA_BF16(cg[i][p*2],   al[i], g0, g2);
                    MMA_BF16(cg[i][p*2+1], ah[i], g1, g3);
                    MMA_BF16(cg[i][p*2+1], ah[i], h1, h3);
                    MMA_BF16(cg[i][p*2+1], al[i], g1, g3);
                    MMA_BF16(cu[i][p*2],   ah[i], u0, u2);
                    MMA_BF16(cu[i][p*2],   ah[i], w0, w2);
                    MMA_BF16(cu[i][p*2],   al[i], u0, u2);
                    MMA_BF16(cu[i][p*2+1], ah[i], u1, u3);
                    MMA_BF16(cu[i][p*2+1], ah[i], w1, w3);
                    MMA_BF16(cu[i][p*2+1], al[i], u1, u3);
                }
            }
        }
    }

    // epilogue: silu(g)*u -> bf16 hi/lo to g_mid
#pragma unroll
    for (int i = 0; i < 4; i++) {
        int r0 = wm*64 + i*16 + (lane >> 2);
#pragma unroll
        for (int hh = 0; hh < 2; hh++) {
            int rr = r0 + hh*8;
            if (m0 + rr < segLen) {
                size_t rowb = (size_t)(seg0 + m0 + rr)*IDIM + n0 + wn*32 + (lane & 3)*2;
#pragma unroll
                for (int j = 0; j < 4; j++) {
                    float gv0 = cg[i][j][hh*2+0], gv1 = cg[i][j][hh*2+1];
                    float uv0 = cu[i][j][hh*2+0], uv1 = cu[i][j][hh*2+1];
                    float v0 = uv0 * gv0 / (1.f + __expf(-gv0));
                    float v1 = uv1 * gv1 / (1.f + __expf(-gv1));
                    __nv_bfloat162 hb = __float22bfloat162_rn(make_float2(v0, v1));
                    float2 hf = __bfloat1622float2(hb);
                    __nv_bfloat162 lb = __float22bfloat162_rn(make_float2(v0 - hf.x, v1 - hf.y));
                    *reinterpret_cast<uint32_t*>(&g_mid_hi[rowb + j*8]) = *reinterpret_cast<uint32_t*>(&hb);
                    *reinterpret_cast<uint32_t*>(&g_mid_lo[rowb + j*8]) = *reinterpret_cast<uint32_t*>(&lb);
                }
            }
        }
    }
}

// ---------------- down bf16x3 mma GEMM ----------------
// stage: AH 0, AL 8192, BH 16384, BL 24576 ; stride 32768 ; 4 stages
#define DN_STG 32768
#define DN_NSTG 4
#define DN_SMEM (DN_NSTG*DN_STG)

__global__ __launch_bounds__(256,1) void down_mma() {
    const int e = blockIdx.z;
    const int seg0 = g_offsets[e];
    const int segLen = g_offsets[e+1] - seg0;
    const int m0 = blockIdx.y * 128;
    if (m0 >= segLen) return;
    const int n0 = blockIdx.x * 128;

    extern __shared__ char smc[];
    const uint32_t sb = smem_u32(smc);
    const int t = threadIdx.x, lane = t & 31, wid = t >> 5;
    const int wm = wid >> 2, wn = wid & 3;
    const int r = t & 127, half = t >> 7;

    const size_t slotrow = (size_t)(seg0 + m0 + r);   // padded arrays make OOB rows safe
    const __nv_bfloat16* sAH = g_mid_hi + slotrow*IDIM;
    const __nv_bfloat16* sAL = g_mid_lo + slotrow*IDIM;
    const size_t wrow = ((size_t)e*HDIM + n0 + r)*IDIM;
    const __nv_bfloat16* sBH = g_wd_hi + wrow;
    const __nv_bfloat16* sBL = g_wd_lo + wrow;

    float c[4][4][4] = {};

    auto load_stage = [&](int ss){
        const uint32_t base = sb + (ss % DN_NSTG)*DN_STG;
        const int k0 = ss*32;
#pragma unroll
        for (int qq = 0; qq < 2; qq++) {
            const int cc = 2*half + qq;
            const uint32_t dsw = SWZ(r, cc);
            const int ko = k0 + cc*8;
            CPA16(base +     0 + dsw, sAH + ko, 16);
            CPA16(base +  8192 + dsw, sAL + ko, 16);
            CPA16(base + 16384 + dsw, sBH + ko, 16);
            CPA16(base + 24576 + dsw, sBL + ko, 16);
        }
        CPA_COMMIT();
    };

    load_stage(0);
    load_stage(1);
    load_stage(2);

#pragma unroll 1
    for (int s = 0; s < 64; ++s) {
        CPA_WAIT(2);
        __syncthreads();
        if (s + 3 < 64) load_stage(s + 3);
        const uint32_t base = sb + (s % DN_NSTG)*DN_STG;
#pragma unroll
        for (int k16 = 0; k16 < 2; k16++) {
            const int hc = lane >> 4, br = lane & 15;
            const int cc = k16*2 + hc;
            uint32_t ah[4][4], al[4][4];
#pragma unroll
            for (int i = 0; i < 4; i++) {
                int row = wm*64 + i*16 + br;
                uint32_t off = SWZ(row, cc);
                LDSM4(ah[i][0],ah[i][1],ah[i][2],ah[i][3], base +    0 + off);
                LDSM4(al[i][0],al[i][1],al[i][2],al[i][3], base + 8192 + off);
            }
#pragma unroll
            for (int p = 0; p < 2; p++) {
                int row = wn*32 + p*16 + br;
                uint32_t off = SWZ(row, cc);
                uint32_t b0,b1,b2,b3, d0,d1,d2,d3;
                LDSM4(b0,b1,b2,b3, base + 16384 + off);
                LDSM4(d0,d1,d2,d3, base + 24576 + off);
#pragma unroll
                for (int i = 0; i < 4; i++) {
                    MMA_BF16(c[i][p*2],   ah[i], b0, b2);
                    MMA_BF16(c[i][p*2],   ah[i], d0, d2);
                    MMA_BF16(c[i][p*2],   al[i], b0, b2);
                    MMA_BF16(c[i][p*2+1], ah[i], b1, b3);
                    MMA_BF16(c[i][p*2+1], ah[i], d1, d3);
                    MMA_BF16(c[i][p*2+1], al[i], b1, b3);
                }
            }
        }
    }

#pragma unroll
    for (int i = 0; i < 4; i++) {
        int r0 = wm*64 + i*16 + (lane >> 2);
#pragma unroll
        for (int hh = 0; hh < 2; hh++) {
            int rr = r0 + hh*8;
            if (m0 + rr < segLen) {
                float* dst = g_down + (size_t)(seg0 + m0 + rr)*HDIM + n0 + wn*32 + (lane & 3)*2;
#pragma unroll
                for (int j = 0; j < 4; j++)
                    *reinterpret_cast<float2*>(dst + j*8) =
                        make_float2(c[i][j][hh*2], c[i][j][hh*2+1]);
            }
        }
    }
}

// ---------------- combine ----------------
__global__ void combine_kernel(float* __restrict__ out) {
    int idx = blockIdx.x * blockDim.x + threadIdx.x;
    if (idx >= NTOK * (HDIM/4)) return;
    int n = idx / (HDIM/4);
    int h = (idx % (HDIM/4)) * 4;
    float w0 = g_topk_w[2*n], w1 = g_topk_w[2*n+1];
    int s0 = g_slot_of[2*n], s1 = g_slot_of[2*n+1];
    float4 a = *reinterpret_cast<const float4*>(&g_down[(size_t)s0*HDIM + h]);
    float4 b = *reinterpret_cast<const float4*>(&g_down[(size_t)s1*HDIM + h]);
    float4 o;
    o.x = w0*a.x + w1*b.x;
    o.y = w0*a.y + w1*b.y;
    o.z = w0*a.z + w1*b.z;
    o.w = w0*a.w + w1*b.w;
    *reinterpret_cast<float4*>(&out[(size_t)n*HDIM + h]) = o;
}

// ---------------- launch ----------------
extern "C" void kernel_launch(void* const* d_in, const int* in_sizes, int n_in,
                              void* d_out, int out_size) {
    const float* x  = (const float*)d_in[0];
    const float* Wr = (const float*)d_in[1];
    const float* Wg = (const float*)d_in[2];
    const float* Wu = (const float*)d_in[3];
    const float* Wd = (const float*)d_in[4];
    float* out = (float*)d_out;

    cudaFuncSetAttribute(gateup_mma, cudaFuncAttributeMaxDynamicSharedMemorySize, GU_SMEM);
    cudaFuncSetAttribute(down_mma,   cudaFuncAttributeMaxDynamicSharedMemorySize, DN_SMEM);

    void* p;
    cudaGetSymbolAddress(&p, g_ctr);
    cudaMemsetAsync(p, 0, sizeof(int)*2*NEXP, 0);

    // pre-split fp32 -> bf16 hi/lo
    void *xh, *xl, *gh, *gl, *uh, *ul, *dh, *dl;
    cudaGetSymbolAddress(&xh, g_x_hi);  cudaGetSymbolAddress(&xl, g_x_lo);
    cudaGetSymbolAddress(&gh, g_wg_hi); cudaGetSymbolAddress(&gl, g_wg_lo);
    cudaGetSymbolAddress(&uh, g_wu_hi); cudaGetSymbolAddress(&ul, g_wu_lo);
    cudaGetSymbolAddress(&dh, g_wd_hi); cudaGetSymbolAddress(&dl, g_wd_lo);

    cvt_kernel<<<2048, 256>>>((const float4*)x,  (uint2*)xh, (uint2*)xl, NTOK*HDIM/4);
    cvt_kernel<<<8192, 256>>>((const float4*)Wg, (uint2*)gh, (uint2*)gl, WELEM/4);
    cvt_kernel<<<8192, 256>>>((const float4*)Wu, (uint2*)uh, (uint2*)ul, WELEM/4);
    cvt_kernel<<<8192, 256>>>((const float4*)Wd, (uint2*)dh, (uint2*)dl, WELEM/4);

    router_kernel<<<NTOK/8, 256>>>(x, Wr);

    float* aux_out = (out_size > NTOK*HDIM) ? (out + (size_t)NTOK*HDIM) : nullptr;
    scan_kernel<<<1, 32>>>(aux_out);

    assign_kernel<<<(NK + 255)/256, 256>>>();

    gateup_mma<<<dim3(IDIM/128, NK/128, NEXP), 256, GU_SMEM>>>();
    down_mma<<<dim3(HDIM/128, NK/128, NEXP), 256, DN_SMEM>>>();

    combine_kernel<<<(NTOK*(HDIM/4) + 255)/256, 256>>>(out);
}